// round 1
// baseline (speedup 1.0000x reference)
#include <cuda_runtime.h>
#include <math.h>

// ---------------- problem dims (fixed) ----------------
#define B2     2
#define CIN    64
#define COUT   128
#define TFULL  8192
#define LH     4096        // T/2
#define DI     256
#define DTR    8
#define NS     16
#define NITER  2           // NM mamba blocks (each fwd+bwd)
#define NCHUNK 64
#define CHUNK  64          // NCHUNK*CHUNK == LH
#define KIM    320         // CIN * 5 (im2col K)

// ---------------- scratch (device globals; no runtime alloc) ----------------
__device__ float g_im   [B2*LH*KIM];          // im2col of x
__device__ float g_h    [B2*LH*COUT];         // running residual h [b][l][c]
__device__ float g_hn   [B2*LH*COUT];         // layernorm(h)
__device__ float g_xz   [B2*LH*2*512];        // [b][l][mp][512]  (xp|z)
__device__ float g_u    [2*B2*LH*DI];         // [mb][tau][d]  mb = mp*2+b
__device__ float g_xdbl [2*B2*LH*40];         // [mp][(b*L+tau)][40]  dt|B|C
__device__ float g_delta[2*B2*LH*DI];         // softplus'ed delta
__device__ float g_s    [2*B2*LH*DI];         // scan output (token order)
__device__ float g_P    [4*NCHUNK*NS*DI];     // chunk products
__device__ float g_q    [4*NCHUNK*NS*DI];     // chunk local states
__device__ float g_hs   [4*NCHUNK*NS*DI];     // chunk start states
__device__ float g_stats[4];                  // GN sum/sumsq per batch

// ---------------- generic NT GEMM: C[i,j] (+)= sum_k A[i,k]*B[j,k] (+bias[j]) ----------------
// M fixed multiple of 64 (8192), K multiple of 16. N guarded.
__global__ __launch_bounds__(256) void gemm_nt(
    const float* __restrict__ A, int lda,
    const float* __restrict__ B, int ldb,
    float* __restrict__ C, int ldc,
    int N, int K, const float* __restrict__ bias, int acc)
{
    __shared__ float As[16][64];
    __shared__ float Bs[16][64];
    const int tid  = threadIdx.x;
    const int brow = blockIdx.x * 64;
    const int bcol = blockIdx.y * 64;
    const int lrow = tid >> 2;            // 0..63
    const int lk   = (tid & 3) << 2;      // 0,4,8,12
    const int tx   = tid & 15, ty = tid >> 4;

    float accv[4][4];
#pragma unroll
    for (int i = 0; i < 4; i++)
#pragma unroll
        for (int j = 0; j < 4; j++) accv[i][j] = 0.f;

    for (int k0 = 0; k0 < K; k0 += 16) {
        float4 av = *(const float4*)(A + (size_t)(brow + lrow) * lda + k0 + lk);
        As[lk + 0][lrow] = av.x; As[lk + 1][lrow] = av.y;
        As[lk + 2][lrow] = av.z; As[lk + 3][lrow] = av.w;
        float4 bv = make_float4(0.f, 0.f, 0.f, 0.f);
        int bj = bcol + lrow;
        if (bj < N) bv = *(const float4*)(B + (size_t)bj * ldb + k0 + lk);
        Bs[lk + 0][lrow] = bv.x; Bs[lk + 1][lrow] = bv.y;
        Bs[lk + 2][lrow] = bv.z; Bs[lk + 3][lrow] = bv.w;
        __syncthreads();
#pragma unroll
        for (int k = 0; k < 16; k++) {
            float4 ra = *(const float4*)&As[k][ty << 2];
            float4 rb = *(const float4*)&Bs[k][tx << 2];
            float aa[4] = {ra.x, ra.y, ra.z, ra.w};
            float bb[4] = {rb.x, rb.y, rb.z, rb.w};
#pragma unroll
            for (int i = 0; i < 4; i++)
#pragma unroll
                for (int j = 0; j < 4; j++) accv[i][j] += aa[i] * bb[j];
        }
        __syncthreads();
    }
#pragma unroll
    for (int i = 0; i < 4; i++) {
        int row = brow + (ty << 2) + i;
#pragma unroll
        for (int j = 0; j < 4; j++) {
            int col = bcol + (tx << 2) + j;
            if (col < N) {
                float v = accv[i][j];
                if (bias) v += bias[col];
                if (acc)  v += C[(size_t)row * ldc + col];
                C[(size_t)row * ldc + col] = v;
            }
        }
    }
}

// ---------------- front end ----------------
__global__ void k_zero_stats() { if (threadIdx.x < 4) g_stats[threadIdx.x] = 0.f; }

__global__ void k_im2col(const float* __restrict__ x)
{
    int idx = blockIdx.x * 256 + threadIdx.x;
    if (idx >= B2 * LH * KIM) return;
    int col = idx % KIM;
    int l   = (idx / KIM) % LH;
    int b   = idx / (KIM * LH);
    int cin = col / 5, k = col % 5;
    int t = 2 * l + k - 2;
    float v = 0.f;
    if (t >= 0 && t < TFULL) v = x[((size_t)b * CIN + cin) * TFULL + t];
    g_im[idx] = v;
}

__global__ __launch_bounds__(256) void k_gn_stats()
{
    int b = blockIdx.y;
    float s = 0.f, q = 0.f;
    for (int i = blockIdx.x * 256 + threadIdx.x; i < LH * COUT; i += gridDim.x * 256) {
        float v = g_h[(size_t)b * LH * COUT + i];
        s += v; q += v * v;
    }
    __shared__ float sh[256], sh2[256];
    sh[threadIdx.x] = s; sh2[threadIdx.x] = q;
    __syncthreads();
    for (int st = 128; st > 0; st >>= 1) {
        if (threadIdx.x < st) { sh[threadIdx.x] += sh[threadIdx.x + st]; sh2[threadIdx.x] += sh2[threadIdx.x + st]; }
        __syncthreads();
    }
    if (threadIdx.x == 0) {
        atomicAdd(&g_stats[b * 2 + 0], sh[0]);
        atomicAdd(&g_stats[b * 2 + 1], sh2[0]);
    }
}

__global__ void k_gn_apply(const float* __restrict__ gn_g, const float* __restrict__ gn_b,
                           const float* __restrict__ prelu_a)
{
    int idx = blockIdx.x * 256 + threadIdx.x;
    if (idx >= B2 * LH * COUT) return;
    int b = idx / (LH * COUT);
    int c = idx % COUT;
    const float inv = 1.f / (float)(LH * COUT);
    float mu  = g_stats[b * 2 + 0] * inv;
    float var = g_stats[b * 2 + 1] * inv - mu * mu;
    float rs  = rsqrtf(var + 1e-5f);
    float v = (g_h[idx] - mu) * rs * gn_g[c] + gn_b[c];
    float al = prelu_a[0];
    g_h[idx] = v >= 0.f ? v : al * v;
}

// ---------------- per-token LayerNorm (warp per token) ----------------
__global__ void k_ln(const float* __restrict__ lg, const float* __restrict__ lb, int it)
{
    int gw = (blockIdx.x * blockDim.x + threadIdx.x) >> 5;
    int lane = threadIdx.x & 31;
    if (gw >= B2 * LH) return;
    const float4 v = *(const float4*)(g_h + (size_t)gw * COUT + lane * 4);
    float s = v.x + v.y + v.z + v.w;
    float q = v.x * v.x + v.y * v.y + v.z * v.z + v.w * v.w;
#pragma unroll
    for (int o = 16; o; o >>= 1) {
        s += __shfl_xor_sync(0xffffffffu, s, o);
        q += __shfl_xor_sync(0xffffffffu, q, o);
    }
    float mu  = s * (1.f / COUT);
    float var = q * (1.f / COUT) - mu * mu;
    float rs  = rsqrtf(var + 1e-5f);
    int c = lane * 4;
    const float* gg = lg + it * COUT;
    const float* gb = lb + it * COUT;
    float4 o4;
    o4.x = (v.x - mu) * rs * gg[c + 0] + gb[c + 0];
    o4.y = (v.y - mu) * rs * gg[c + 1] + gb[c + 1];
    o4.z = (v.z - mu) * rs * gg[c + 2] + gb[c + 2];
    o4.w = (v.w - mu) * rs * gg[c + 3] + gb[c + 3];
    *(float4*)(g_hn + (size_t)gw * COUT + c) = o4;
}

// ---------------- depthwise causal conv1d + silu -> u (scan-time order) ----------------
__global__ void k_conv1d(const float* __restrict__ cw, const float* __restrict__ cb, int it)
{
    int idx = blockIdx.x * 256 + threadIdx.x;     // total 2^23
    int d   = idx & 255;
    int tau = (idx >> 8) & (LH - 1);
    int b   = (idx >> 20) & 1;
    int mp  = (idx >> 21) & 1;
    int m   = 2 * it + mp;
    float acc = cb[m * DI + d];
    const float* w = cw + (size_t)(m * DI + d) * 4;
#pragma unroll
    for (int k = 0; k < 4; k++) {
        int tt = tau - 3 + k;
        if (tt >= 0) {
            int tok = mp ? (LH - 1 - tt) : tt;
            acc += w[k] * g_xz[(((size_t)b * LH + tok) * 2 + mp) * 512 + d];
        }
    }
    float u = acc / (1.f + __expf(-acc));   // silu
    g_u[idx] = u;
}

// ---------------- delta = softplus(dt @ W_dt^T + b_dt) ----------------
__global__ __launch_bounds__(256) void k_delta(const float* __restrict__ Wd,
                                               const float* __restrict__ bd, int it)
{
    __shared__ float dts[16][8];
    int tau0 = blockIdx.x * 16;
    int b  = blockIdx.y;
    int mp = blockIdx.z;
    int m  = 2 * it + mp;
    int d  = threadIdx.x;
    if (threadIdx.x < 128) {
        int t = threadIdx.x >> 3, r = threadIdx.x & 7;
        dts[t][r] = g_xdbl[((size_t)mp * (B2 * LH) + b * LH + tau0 + t) * 40 + r];
    }
    __syncthreads();
    float w[8];
#pragma unroll
    for (int r = 0; r < 8; r++) w[r] = Wd[(size_t)(m * DI + d) * 8 + r];
    float bias = bd[m * DI + d];
    int mb = mp * 2 + b;
#pragma unroll
    for (int t = 0; t < 16; t++) {
        float p = bias;
#pragma unroll
        for (int r = 0; r < 8; r++) p += dts[t][r] * w[r];
        float dl = (p > 20.f) ? p : log1pf(__expf(p));
        g_delta[((size_t)mb * LH + tau0 + t) * DI + d] = dl;
    }
}

// ---------------- scan pass 1: per-chunk local state q and product P ----------------
__global__ __launch_bounds__(256) void scan_pass1(const float* __restrict__ A_log, int it)
{
    int chunk = blockIdx.x, b = blockIdx.y, mp = blockIdx.z;
    int m = 2 * it + mp;
    int d = threadIdx.x;
    int mb = mp * 2 + b;
    float a[16], h[16], P[16];
#pragma unroll
    for (int n = 0; n < NS; n++) {
        a[n] = -__expf(A_log[((size_t)m * DI + d) * NS + n]);
        h[n] = 0.f; P[n] = 1.f;
    }
    __shared__ float Bsm[16][16];
    int tau0 = chunk * CHUNK;
    const float* dl = g_delta + ((size_t)mb * LH + tau0) * DI + d;
    const float* ul = g_u     + ((size_t)mb * LH + tau0) * DI + d;
    const float* xb = g_xdbl  + ((size_t)mp * (B2 * LH) + b * LH + tau0) * 40;
    for (int tt = 0; tt < CHUNK; tt += 16) {
        {
            int t = threadIdx.x >> 4, n = threadIdx.x & 15;
            Bsm[t][n] = xb[(size_t)(tt + t) * 40 + 8 + n];
        }
        __syncthreads();
#pragma unroll 4
        for (int t = 0; t < 16; t++) {
            float delta = dl[(size_t)(tt + t) * DI];
            float du = delta * ul[(size_t)(tt + t) * DI];
#pragma unroll
            for (int n = 0; n < NS; n++) {
                float dA = __expf(delta * a[n]);
                P[n] *= dA;
                h[n] = dA * h[n] + du * Bsm[t][n];
            }
        }
        __syncthreads();
    }
    size_t base = ((size_t)(mb * NCHUNK + chunk) * NS) * DI + d;
#pragma unroll
    for (int n = 0; n < NS; n++) {
        g_q[base + (size_t)n * DI] = h[n];
        g_P[base + (size_t)n * DI] = P[n];
    }
}

// ---------------- scan pass 2: sequential combine over chunks ----------------
__global__ void scan_pass2()
{
    int id = blockIdx.x * 256 + threadIdx.x;    // 4*16*256 = 16384
    int d  = id & 255;
    int n  = (id >> 8) & 15;
    int mb = id >> 12;
    float h = 0.f;
    for (int c = 0; c < NCHUNK; c++) {
        size_t ix = ((size_t)(mb * NCHUNK + c) * NS + n) * DI + d;
        g_hs[ix] = h;
        h = g_P[ix] * h + g_q[ix];
    }
}

// ---------------- scan pass 3: recompute with true start state, emit s ----------------
__global__ __launch_bounds__(256) void scan_pass3(const float* __restrict__ A_log,
                                                  const float* __restrict__ Dp, int it)
{
    int chunk = blockIdx.x, b = blockIdx.y, mp = blockIdx.z;
    int m = 2 * it + mp;
    int d = threadIdx.x;
    int mb = mp * 2 + b;
    float a[16], h[16];
#pragma unroll
    for (int n = 0; n < NS; n++) {
        a[n] = -__expf(A_log[((size_t)m * DI + d) * NS + n]);
        h[n] = g_hs[((size_t)(mb * NCHUNK + chunk) * NS + n) * DI + d];
    }
    float Dv = Dp[m * DI + d];
    __shared__ float Bsm[16][16], Csm[16][16];
    int tau0 = chunk * CHUNK;
    const float* dl = g_delta + ((size_t)mb * LH + tau0) * DI + d;
    const float* ul = g_u     + ((size_t)mb * LH + tau0) * DI + d;
    const float* xb = g_xdbl  + ((size_t)mp * (B2 * LH) + b * LH + tau0) * 40;
    for (int tt = 0; tt < CHUNK; tt += 16) {
        {
            int t = threadIdx.x >> 4, n = threadIdx.x & 15;
            Bsm[t][n] = xb[(size_t)(tt + t) * 40 + 8  + n];
            Csm[t][n] = xb[(size_t)(tt + t) * 40 + 24 + n];
        }
        __syncthreads();
#pragma unroll 4
        for (int t = 0; t < 16; t++) {
            int tau = tau0 + tt + t;
            float delta = dl[(size_t)(tt + t) * DI];
            float u = ul[(size_t)(tt + t) * DI];
            float du = delta * u;
            float y = 0.f;
#pragma unroll
            for (int n = 0; n < NS; n++) {
                float dA = __expf(delta * a[n]);
                h[n] = dA * h[n] + du * Bsm[t][n];
                y += h[n] * Csm[t][n];
            }
            int tok = mp ? (LH - 1 - tau) : tau;
            float z = g_xz[(((size_t)b * LH + tok) * 2 + mp) * 512 + 256 + d];
            float sil = z / (1.f + __expf(-z));
            g_s[((size_t)mb * LH + tok) * DI + d] = (y + u * Dv) * sil;
        }
        __syncthreads();
    }
}

// ---------------- final transpose [b][l][c] -> [b][c][l] ----------------
__global__ void k_transpose(float* __restrict__ out)
{
    __shared__ float tile[32][33];
    int b = blockIdx.z;
    int l0 = blockIdx.x * 32, c0 = blockIdx.y * 32;
    int tx = threadIdx.x, ty = threadIdx.y;
#pragma unroll
    for (int j = 0; j < 32; j += 8)
        tile[ty + j][tx] = g_h[((size_t)b * LH + l0 + ty + j) * COUT + c0 + tx];
    __syncthreads();
#pragma unroll
    for (int j = 0; j < 32; j += 8)
        out[((size_t)b * COUT + c0 + ty + j) * LH + l0 + tx] = tile[tx][ty + j];
}

// ---------------- host orchestration ----------------
static float* symaddr(const void* sym)
{
    void* p = nullptr;
    cudaGetSymbolAddress(&p, sym);
    return (float*)p;
}

extern "C" void kernel_launch(void* const* d_in, const int* in_sizes, int n_in,
                              void* d_out, int out_size)
{
    const float* x        = (const float*)d_in[0];
    const float* conv_w   = (const float*)d_in[1];
    const float* conv_b   = (const float*)d_in[2];
    const float* gn_g     = (const float*)d_in[3];
    const float* gn_b     = (const float*)d_in[4];
    const float* prelu_a  = (const float*)d_in[5];
    const float* ln_g     = (const float*)d_in[6];
    const float* ln_b     = (const float*)d_in[7];
    const float* W_in     = (const float*)d_in[8];
    const float* conv1d_w = (const float*)d_in[9];
    const float* conv1d_b = (const float*)d_in[10];
    const float* W_xproj  = (const float*)d_in[11];
    const float* W_dt     = (const float*)d_in[12];
    const float* b_dt     = (const float*)d_in[13];
    const float* A_log    = (const float*)d_in[14];
    const float* D_param  = (const float*)d_in[15];
    const float* W_out    = (const float*)d_in[16];
    float* out = (float*)d_out;

    float* p_im   = symaddr(g_im);
    float* p_h    = symaddr(g_h);
    float* p_hn   = symaddr(g_hn);
    float* p_xz   = symaddr(g_xz);
    float* p_u    = symaddr(g_u);
    float* p_xdbl = symaddr(g_xdbl);
    float* p_s    = symaddr(g_s);

    const int M = B2 * LH;   // 8192 rows everywhere

    // ---- front end: conv (im2col + GEMM) -> GroupNorm -> PReLU ----
    k_zero_stats<<<1, 32>>>();
    k_im2col<<<(B2 * LH * KIM + 255) / 256, 256>>>(x);
    gemm_nt<<<dim3(M / 64, COUT / 64), 256>>>(p_im, KIM, conv_w, KIM,
                                              p_h, COUT, COUT, KIM, conv_b, 0);
    k_gn_stats<<<dim3(64, B2), 256>>>();
    k_gn_apply<<<(B2 * LH * COUT + 255) / 256, 256>>>(gn_g, gn_b, prelu_a);

    // ---- bidirectional mamba blocks ----
    for (int it = 0; it < NITER; ++it) {
        k_ln<<<(M * 32 + 255) / 256, 256>>>(ln_g, ln_b, it);

        // xz = hn @ [W_in[2it] ; W_in[2it+1]]^T  -> [b][l][mp][512]
        gemm_nt<<<dim3(M / 64, 1024 / 64), 256>>>(p_hn, COUT,
                                                  W_in + (size_t)it * 2 * 512 * COUT, COUT,
                                                  p_xz, 1024, 1024, COUT, nullptr, 0);

        // depthwise causal conv + silu (both directions)
        k_conv1d<<<(2 * B2 * LH * DI) / 256, 256>>>(conv1d_w, conv1d_b, it);

        // xdbl = u @ W_xproj^T   (per direction)
        for (int mp = 0; mp < 2; mp++) {
            int m = 2 * it + mp;
            gemm_nt<<<dim3(M / 64, 1), 256>>>(p_u + (size_t)mp * M * DI, DI,
                                              W_xproj + (size_t)m * 40 * DI, DI,
                                              p_xdbl + (size_t)mp * M * 40, 40,
                                              40, DI, nullptr, 0);
        }

        k_delta<<<dim3(LH / 16, B2, 2), 256>>>(W_dt, b_dt, it);

        scan_pass1<<<dim3(NCHUNK, B2, 2), 256>>>(A_log, it);
        scan_pass2<<<64, 256>>>();
        scan_pass3<<<dim3(NCHUNK, B2, 2), 256>>>(A_log, D_param, it);

        // h += s @ W_out^T  (both directions, accumulate)
        for (int mp = 0; mp < 2; mp++) {
            int m = 2 * it + mp;
            gemm_nt<<<dim3(M / 64, COUT / 64), 256>>>(p_s + (size_t)mp * M * DI, DI,
                                                      W_out + (size_t)m * COUT * DI, DI,
                                                      p_h, COUT, COUT, DI, nullptr, 1);
        }
    }

    // ---- output transpose [b][l][c] -> [b][c][l] ----
    k_transpose<<<dim3(LH / 32, COUT / 32, B2), dim3(32, 8)>>>(out);
}

// round 2
// speedup vs baseline: 1.0535x; 1.0535x over previous
#include <cuda_runtime.h>
#include <math.h>

// ---------------- problem dims (fixed) ----------------
#define B2     2
#define CIN    64
#define COUT   128
#define TFULL  8192
#define LH     4096        // T/2
#define DI     256
#define DTR    8
#define NS     16
#define NITER  2           // NM mamba blocks (each fwd+bwd)
#define NCHUNK 128
#define CHUNK  32          // NCHUNK*CHUNK == LH
#define KIM    320         // CIN * 5 (im2col K)

// ---------------- scratch (device globals; no runtime alloc) ----------------
__device__ float g_im   [B2*LH*KIM];          // im2col of x
__device__ float g_h    [B2*LH*COUT];         // running residual h [b][l][c]
__device__ float g_hn   [B2*LH*COUT];         // layernorm(h)
__device__ float g_xz   [B2*LH*2*512];        // [b][l][mp][512]  (xp|z)
__device__ float g_u    [2*B2*LH*DI];         // [mb][tau][d]  mb = mp*2+b
__device__ float g_xdbl [2*B2*LH*40];         // [mp][(b*L+tau)][40]  dt|B|C
__device__ float g_delta[2*B2*LH*DI];         // softplus'ed delta
__device__ float g_s    [2*B2*LH*DI];         // scan output (token order)
__device__ float g_P    [4*NCHUNK*NS*DI];     // chunk products
__device__ float g_q    [4*NCHUNK*NS*DI];     // chunk local states
__device__ float g_hs   [4*NCHUNK*NS*DI];     // chunk start states
__device__ float g_stats[4];                  // GN sum/sumsq per batch

// ---------------- tiled NT GEMM: C[i,j] (+)= sum_k A[i,k]*B[j,k] ----------------
// EPI: 0 = plain (+optional bias), 1 = bias + GroupNorm stats, 2 = accumulate into C
// 256 threads. BM|M (M=8192), BK|K. N guarded on loads/stores.
template<int BM, int BN, int BK, int TM, int TN, int EPI>
__global__ __launch_bounds__(256, 2) void gemm_t(
    const float* __restrict__ A, int lda, long long aB,
    const float* __restrict__ B, int ldb, long long bB,
    float* __restrict__ C, int ldc, long long cB,
    int N, int K, const float* __restrict__ bias)
{
    constexpr int PAD = 4;
    constexpr int KV  = BK / 4;            // float4s per k-panel row
    constexpr int AV  = BM * KV / 256;     // A vec-loads per thread
    constexpr int BV  = BN * KV / 256;     // B vec-loads per thread

    __shared__ float As[2][BK][BM + PAD];
    __shared__ float Bs[2][BK][BN + PAD];

    const int tid  = threadIdx.x;
    const int tx   = tid % (BN / TN);
    const int ty   = tid / (BN / TN);
    const int brow = blockIdx.x * BM;
    const int bcol = blockIdx.y * BN;

    A += (long long)blockIdx.z * aB;
    B += (long long)blockIdx.z * bB;
    C += (long long)blockIdx.z * cB;

    float4 ar[AV], br[BV];

    auto loadA = [&](int k0) {
#pragma unroll
        for (int i = 0; i < AV; i++) {
            int v = tid + i * 256;
            int row = v / KV, k4 = (v % KV) * 4;
            ar[i] = *(const float4*)(A + (long long)(brow + row) * lda + k0 + k4);
        }
    };
    auto loadB = [&](int k0) {
#pragma unroll
        for (int i = 0; i < BV; i++) {
            int v = tid + i * 256;
            int row = v / KV, k4 = (v % KV) * 4;
            int gj = bcol + row;
            br[i] = (gj < N) ? *(const float4*)(B + (long long)gj * ldb + k0 + k4)
                             : make_float4(0.f, 0.f, 0.f, 0.f);
        }
    };
    auto storeAB = [&](int buf) {
#pragma unroll
        for (int i = 0; i < AV; i++) {
            int v = tid + i * 256;
            int row = v / KV, k4 = (v % KV) * 4;
            As[buf][k4 + 0][row] = ar[i].x; As[buf][k4 + 1][row] = ar[i].y;
            As[buf][k4 + 2][row] = ar[i].z; As[buf][k4 + 3][row] = ar[i].w;
        }
#pragma unroll
        for (int i = 0; i < BV; i++) {
            int v = tid + i * 256;
            int row = v / KV, k4 = (v % KV) * 4;
            Bs[buf][k4 + 0][row] = br[i].x; Bs[buf][k4 + 1][row] = br[i].y;
            Bs[buf][k4 + 2][row] = br[i].z; Bs[buf][k4 + 3][row] = br[i].w;
        }
    };

    float acc[TM][TN];
#pragma unroll
    for (int i = 0; i < TM; i++)
#pragma unroll
        for (int j = 0; j < TN; j++) acc[i][j] = 0.f;

    loadA(0); loadB(0);
    storeAB(0);
    __syncthreads();

    const int nt = K / BK;
    for (int kt = 0; kt < nt; kt++) {
        int cur = kt & 1;
        if (kt + 1 < nt) { loadA((kt + 1) * BK); loadB((kt + 1) * BK); }
#pragma unroll
        for (int k = 0; k < BK; k++) {
            float a[TM], b[TN];
#pragma unroll
            for (int i = 0; i < TM; i += 4)
                *(float4*)&a[i] = *(const float4*)&As[cur][k][ty * TM + i];
#pragma unroll
            for (int j = 0; j < TN; j += 4)
                *(float4*)&b[j] = *(const float4*)&Bs[cur][k][tx * TN + j];
#pragma unroll
            for (int i = 0; i < TM; i++)
#pragma unroll
                for (int j = 0; j < TN; j++)
                    acc[i][j] += a[i] * b[j];
        }
        if (kt + 1 < nt) storeAB(cur ^ 1);
        __syncthreads();
    }

    float s = 0.f, q = 0.f;
#pragma unroll
    for (int i = 0; i < TM; i++) {
        long long row = brow + ty * TM + i;
#pragma unroll
        for (int j = 0; j < TN; j += 4) {
            int col = bcol + tx * TN + j;
            if (col < N) {
                float4 v = make_float4(acc[i][j], acc[i][j+1], acc[i][j+2], acc[i][j+3]);
                if (bias) {
                    v.x += bias[col + 0]; v.y += bias[col + 1];
                    v.z += bias[col + 2]; v.w += bias[col + 3];
                }
                if (EPI == 2) {
                    float4 o = *(const float4*)(C + row * ldc + col);
                    v.x += o.x; v.y += o.y; v.z += o.z; v.w += o.w;
                }
                if (EPI == 1) {
                    s += v.x + v.y + v.z + v.w;
                    q += v.x*v.x + v.y*v.y + v.z*v.z + v.w*v.w;
                }
                *(float4*)(C + row * ldc + col) = v;
            }
        }
    }

    if (EPI == 1) {
        __syncthreads();
        float* red = (float*)As;
        red[tid] = s; red[256 + tid] = q;
        __syncthreads();
        for (int st = 128; st > 0; st >>= 1) {
            if (tid < st) { red[tid] += red[tid + st]; red[256 + tid] += red[256 + tid + st]; }
            __syncthreads();
        }
        if (tid == 0) {
            int batch = brow >> 12;   // /4096 (BM divides LH)
            atomicAdd(&g_stats[batch * 2 + 0], red[0]);
            atomicAdd(&g_stats[batch * 2 + 1], red[256]);
        }
    }
}

// ---------------- front end ----------------
__global__ void k_zero_stats() { if (threadIdx.x < 4) g_stats[threadIdx.x] = 0.f; }

__global__ void k_im2col(const float* __restrict__ x)
{
    int idx = blockIdx.x * 256 + threadIdx.x;
    if (idx >= B2 * LH * KIM) return;
    int col = idx % KIM;
    int l   = (idx / KIM) % LH;
    int b   = idx / (KIM * LH);
    int cin = col / 5, k = col % 5;
    int t = 2 * l + k - 2;
    float v = 0.f;
    if (t >= 0 && t < TFULL) v = x[((size_t)b * CIN + cin) * TFULL + t];
    g_im[idx] = v;
}

__global__ void k_gn_apply(const float* __restrict__ gn_g, const float* __restrict__ gn_b,
                           const float* __restrict__ prelu_a)
{
    int idx = blockIdx.x * 256 + threadIdx.x;
    if (idx >= B2 * LH * COUT) return;
    int b = idx / (LH * COUT);
    int c = idx % COUT;
    const float inv = 1.f / (float)(LH * COUT);
    float mu  = g_stats[b * 2 + 0] * inv;
    float var = g_stats[b * 2 + 1] * inv - mu * mu;
    float rs  = rsqrtf(var + 1e-5f);
    float v = (g_h[idx] - mu) * rs * gn_g[c] + gn_b[c];
    float al = prelu_a[0];
    g_h[idx] = v >= 0.f ? v : al * v;
}

// ---------------- per-token LayerNorm (warp per token) ----------------
__global__ void k_ln(const float* __restrict__ lg, const float* __restrict__ lb, int it)
{
    int gw = (blockIdx.x * blockDim.x + threadIdx.x) >> 5;
    int lane = threadIdx.x & 31;
    if (gw >= B2 * LH) return;
    const float4 v = *(const float4*)(g_h + (size_t)gw * COUT + lane * 4);
    float s = v.x + v.y + v.z + v.w;
    float q = v.x * v.x + v.y * v.y + v.z * v.z + v.w * v.w;
#pragma unroll
    for (int o = 16; o; o >>= 1) {
        s += __shfl_xor_sync(0xffffffffu, s, o);
        q += __shfl_xor_sync(0xffffffffu, q, o);
    }
    float mu  = s * (1.f / COUT);
    float var = q * (1.f / COUT) - mu * mu;
    float rs  = rsqrtf(var + 1e-5f);
    int c = lane * 4;
    const float* gg = lg + it * COUT;
    const float* gb = lb + it * COUT;
    float4 o4;
    o4.x = (v.x - mu) * rs * gg[c + 0] + gb[c + 0];
    o4.y = (v.y - mu) * rs * gg[c + 1] + gb[c + 1];
    o4.z = (v.z - mu) * rs * gg[c + 2] + gb[c + 2];
    o4.w = (v.w - mu) * rs * gg[c + 3] + gb[c + 3];
    *(float4*)(g_hn + (size_t)gw * COUT + c) = o4;
}

// ---------------- depthwise causal conv1d + silu -> u (scan-time order) ----------------
__global__ void k_conv1d(const float* __restrict__ cw, const float* __restrict__ cb, int it)
{
    int idx = blockIdx.x * 256 + threadIdx.x;     // total 2^23
    int d   = idx & 255;
    int tau = (idx >> 8) & (LH - 1);
    int b   = (idx >> 20) & 1;
    int mp  = (idx >> 21) & 1;
    int m   = 2 * it + mp;
    float acc = cb[m * DI + d];
    const float* w = cw + (size_t)(m * DI + d) * 4;
#pragma unroll
    for (int k = 0; k < 4; k++) {
        int tt = tau - 3 + k;
        if (tt >= 0) {
            int tok = mp ? (LH - 1 - tt) : tt;
            acc += w[k] * g_xz[(((size_t)b * LH + tok) * 2 + mp) * 512 + d];
        }
    }
    float u = acc / (1.f + __expf(-acc));   // silu
    g_u[idx] = u;
}

// ---------------- delta = softplus(dt @ W_dt^T + b_dt) ----------------
__global__ __launch_bounds__(256) void k_delta(const float* __restrict__ Wd,
                                               const float* __restrict__ bd, int it)
{
    __shared__ float dts[16][8];
    int tau0 = blockIdx.x * 16;
    int b  = blockIdx.y;
    int mp = blockIdx.z;
    int m  = 2 * it + mp;
    int d  = threadIdx.x;
    if (threadIdx.x < 128) {
        int t = threadIdx.x >> 3, r = threadIdx.x & 7;
        dts[t][r] = g_xdbl[((size_t)mp * (B2 * LH) + b * LH + tau0 + t) * 40 + r];
    }
    __syncthreads();
    float w[8];
#pragma unroll
    for (int r = 0; r < 8; r++) w[r] = Wd[(size_t)(m * DI + d) * 8 + r];
    float bias = bd[m * DI + d];
    int mb = mp * 2 + b;
#pragma unroll
    for (int t = 0; t < 16; t++) {
        float p = bias;
#pragma unroll
        for (int r = 0; r < 8; r++) p += dts[t][r] * w[r];
        float dl = (p > 20.f) ? p : log1pf(__expf(p));
        g_delta[((size_t)mb * LH + tau0 + t) * DI + d] = dl;
    }
}

// ---------------- scan pass 1: per-chunk local state q and product P ----------------
__global__ __launch_bounds__(256) void scan_pass1(const float* __restrict__ A_log, int it)
{
    int chunk = blockIdx.x, b = blockIdx.y, mp = blockIdx.z;
    int m = 2 * it + mp;
    int d = threadIdx.x;
    int mb = mp * 2 + b;
    float a[16], h[16], P[16];
#pragma unroll
    for (int n = 0; n < NS; n++) {
        a[n] = -__expf(A_log[((size_t)m * DI + d) * NS + n]);
        h[n] = 0.f; P[n] = 1.f;
    }
    __shared__ float Bsm[16][16];
    int tau0 = chunk * CHUNK;
    const float* dl = g_delta + ((size_t)mb * LH + tau0) * DI + d;
    const float* ul = g_u     + ((size_t)mb * LH + tau0) * DI + d;
    const float* xb = g_xdbl  + ((size_t)mp * (B2 * LH) + b * LH + tau0) * 40;
    for (int tt = 0; tt < CHUNK; tt += 16) {
        {
            int t = threadIdx.x >> 4, n = threadIdx.x & 15;
            Bsm[t][n] = xb[(size_t)(tt + t) * 40 + 8 + n];
        }
        __syncthreads();
#pragma unroll 4
        for (int t = 0; t < 16; t++) {
            float delta = dl[(size_t)(tt + t) * DI];
            float du = delta * ul[(size_t)(tt + t) * DI];
#pragma unroll
            for (int n = 0; n < NS; n++) {
                float dA = __expf(delta * a[n]);
                P[n] *= dA;
                h[n] = dA * h[n] + du * Bsm[t][n];
            }
        }
        __syncthreads();
    }
    size_t base = ((size_t)(mb * NCHUNK + chunk) * NS) * DI + d;
#pragma unroll
    for (int n = 0; n < NS; n++) {
        g_q[base + (size_t)n * DI] = h[n];
        g_P[base + (size_t)n * DI] = P[n];
    }
}

// ---------------- scan pass 2: sequential combine over chunks ----------------
__global__ void scan_pass2()
{
    int id = blockIdx.x * 256 + threadIdx.x;    // 4*16*256 = 16384
    int d  = id & 255;
    int n  = (id >> 8) & 15;
    int mb = id >> 12;
    float h = 0.f;
    for (int c = 0; c < NCHUNK; c++) {
        size_t ix = ((size_t)(mb * NCHUNK + c) * NS + n) * DI + d;
        g_hs[ix] = h;
        h = g_P[ix] * h + g_q[ix];
    }
}

// ---------------- scan pass 3: recompute with true start state, emit s ----------------
__global__ __launch_bounds__(256) void scan_pass3(const float* __restrict__ A_log,
                                                  const float* __restrict__ Dp, int it)
{
    int chunk = blockIdx.x, b = blockIdx.y, mp = blockIdx.z;
    int m = 2 * it + mp;
    int d = threadIdx.x;
    int mb = mp * 2 + b;
    float a[16], h[16];
#pragma unroll
    for (int n = 0; n < NS; n++) {
        a[n] = -__expf(A_log[((size_t)m * DI + d) * NS + n]);
        h[n] = g_hs[((size_t)(mb * NCHUNK + chunk) * NS + n) * DI + d];
    }
    float Dv = Dp[m * DI + d];
    __shared__ float Bsm[16][16], Csm[16][16];
    int tau0 = chunk * CHUNK;
    const float* dl = g_delta + ((size_t)mb * LH + tau0) * DI + d;
    const float* ul = g_u     + ((size_t)mb * LH + tau0) * DI + d;
    const float* xb = g_xdbl  + ((size_t)mp * (B2 * LH) + b * LH + tau0) * 40;
    for (int tt = 0; tt < CHUNK; tt += 16) {
        {
            int t = threadIdx.x >> 4, n = threadIdx.x & 15;
            Bsm[t][n] = xb[(size_t)(tt + t) * 40 + 8  + n];
            Csm[t][n] = xb[(size_t)(tt + t) * 40 + 24 + n];
        }
        __syncthreads();
#pragma unroll 4
        for (int t = 0; t < 16; t++) {
            int tau = tau0 + tt + t;
            float delta = dl[(size_t)(tt + t) * DI];
            float u = ul[(size_t)(tt + t) * DI];
            float du = delta * u;
            float y = 0.f;
#pragma unroll
            for (int n = 0; n < NS; n++) {
                float dA = __expf(delta * a[n]);
                h[n] = dA * h[n] + du * Bsm[t][n];
                y += h[n] * Csm[t][n];
            }
            int tok = mp ? (LH - 1 - tau) : tau;
            float z = g_xz[(((size_t)b * LH + tok) * 2 + mp) * 512 + 256 + d];
            float sil = z / (1.f + __expf(-z));
            g_s[((size_t)mb * LH + tok) * DI + d] = (y + u * Dv) * sil;
        }
        __syncthreads();
    }
}

// ---------------- final transpose [b][l][c] -> [b][c][l] ----------------
__global__ void k_transpose(float* __restrict__ out)
{
    __shared__ float tile[32][33];
    int b = blockIdx.z;
    int l0 = blockIdx.x * 32, c0 = blockIdx.y * 32;
    int tx = threadIdx.x, ty = threadIdx.y;
#pragma unroll
    for (int j = 0; j < 32; j += 8)
        tile[ty + j][tx] = g_h[((size_t)b * LH + l0 + ty + j) * COUT + c0 + tx];
    __syncthreads();
#pragma unroll
    for (int j = 0; j < 32; j += 8)
        out[((size_t)b * COUT + c0 + ty + j) * LH + l0 + tx] = tile[tx][ty + j];
}

// ---------------- host orchestration ----------------
static float* symaddr(const void* sym)
{
    void* p = nullptr;
    cudaGetSymbolAddress(&p, sym);
    return (float*)p;
}

extern "C" void kernel_launch(void* const* d_in, const int* in_sizes, int n_in,
                              void* d_out, int out_size)
{
    const float* x        = (const float*)d_in[0];
    const float* conv_w   = (const float*)d_in[1];
    const float* conv_b   = (const float*)d_in[2];
    const float* gn_g     = (const float*)d_in[3];
    const float* gn_b     = (const float*)d_in[4];
    const float* prelu_a  = (const float*)d_in[5];
    const float* ln_g     = (const float*)d_in[6];
    const float* ln_b     = (const float*)d_in[7];
    const float* W_in     = (const float*)d_in[8];
    const float* conv1d_w = (const float*)d_in[9];
    const float* conv1d_b = (const float*)d_in[10];
    const float* W_xproj  = (const float*)d_in[11];
    const float* W_dt     = (const float*)d_in[12];
    const float* b_dt     = (const float*)d_in[13];
    const float* A_log    = (const float*)d_in[14];
    const float* D_param  = (const float*)d_in[15];
    const float* W_out    = (const float*)d_in[16];
    float* out = (float*)d_out;

    float* p_im   = symaddr(g_im);
    float* p_h    = symaddr(g_h);
    float* p_hn   = symaddr(g_hn);
    float* p_xz   = symaddr(g_xz);
    float* p_u    = symaddr(g_u);
    float* p_xdbl = symaddr(g_xdbl);
    float* p_s    = symaddr(g_s);

    const int M = B2 * LH;   // 8192 rows everywhere

    // ---- front end: conv (im2col + GEMM w/ fused GN stats) -> GN apply + PReLU ----
    k_zero_stats<<<1, 32>>>();
    k_im2col<<<(B2 * LH * KIM + 255) / 256, 256>>>(x);
    // conv GEMM: M=8192, N=128, K=320; 64x128 tiles -> 128 blocks; EPI=1 (bias+stats)
    gemm_t<64, 128, 16, 4, 8, 1><<<dim3(M / 64, 1, 1), 256>>>(
        p_im, KIM, 0, conv_w, KIM, 0, p_h, COUT, 0, COUT, KIM, conv_b);
    k_gn_apply<<<(B2 * LH * COUT + 255) / 256, 256>>>(gn_g, gn_b, prelu_a);

    // ---- bidirectional mamba blocks ----
    for (int it = 0; it < NITER; ++it) {
        k_ln<<<(M * 32 + 255) / 256, 256>>>(ln_g, ln_b, it);

        // xz = hn @ [W_in[2it] ; W_in[2it+1]]^T -> [b][l][mp][512]; 128x128 tiles
        gemm_t<128, 128, 16, 8, 8, 0><<<dim3(M / 128, 1024 / 128, 1), 256>>>(
            p_hn, COUT, 0,
            W_in + (size_t)it * 2 * 512 * COUT, COUT, 0,
            p_xz, 1024, 0, 1024, COUT, nullptr);

        // depthwise causal conv + silu (both directions)
        k_conv1d<<<(2 * B2 * LH * DI) / 256, 256>>>(conv1d_w, conv1d_b, it);

        // xdbl = u @ W_xproj^T (both directions batched via z); 128x64 tiles
        gemm_t<128, 64, 16, 8, 4, 0><<<dim3(M / 128, 1, 2), 256>>>(
            p_u, DI, (long long)2 * LH * DI,
            W_xproj + (size_t)(2 * it) * 40 * DI, DI, (long long)40 * DI,
            p_xdbl, 40, (long long)B2 * LH * 40,
            40, DI, nullptr);

        k_delta<<<dim3(LH / 16, B2, 2), 256>>>(W_dt, b_dt, it);

        scan_pass1<<<dim3(NCHUNK, B2, 2), 256>>>(A_log, it);
        scan_pass2<<<64, 256>>>();
        scan_pass3<<<dim3(NCHUNK, B2, 2), 256>>>(A_log, D_param, it);

        // h += s @ W_out^T (both directions, accumulate); 64x128 tiles -> 128 blocks
        for (int mp = 0; mp < 2; mp++) {
            int m = 2 * it + mp;
            gemm_t<64, 128, 16, 4, 8, 2><<<dim3(M / 64, 1, 1), 256>>>(
                p_s + (size_t)mp * 2 * LH * DI, DI, 0,
                W_out + (size_t)m * COUT * DI, DI, 0,
                p_h, COUT, 0, COUT, DI, nullptr);
        }
    }

    // ---- output transpose [b][l][c] -> [b][c][l] ----
    k_transpose<<<dim3(LH / 32, COUT / 32, B2), dim3(32, 8)>>>(out);
}

// round 4
// speedup vs baseline: 1.3937x; 1.3230x over previous
#include <cuda_runtime.h>
#include <cuda_bf16.h>
#include <math.h>
#include <stdint.h>

typedef __nv_bfloat16 bf16;

// ---------------- problem dims (fixed) ----------------
#define B2     2
#define CIN    64
#define COUT   128
#define TFULL  8192
#define LH     4096        // T/2
#define DI     256
#define NS     16
#define NITER  2
#define NCHUNK 128
#define CHUNK  32
#define KIM    320         // CIN * 5 (im2col K)

// ---------------- scratch (device globals) ----------------
__device__ bf16  g_im_h [B2*LH*KIM];
__device__ bf16  g_im_l [B2*LH*KIM];
__device__ float g_h    [B2*LH*COUT];
__device__ bf16  g_hn_h [B2*LH*COUT];
__device__ bf16  g_hn_l [B2*LH*COUT];
__device__ float g_xz   [B2*LH*2*512];
__device__ float g_u    [2*B2*LH*DI];
__device__ bf16  g_u_h  [2*B2*LH*DI];
__device__ bf16  g_u_l  [2*B2*LH*DI];
__device__ float g_xdbl [2*B2*LH*40];
__device__ float g_delta[2*B2*LH*DI];
__device__ bf16  g_s_h  [2*B2*LH*DI];
__device__ bf16  g_s_l  [2*B2*LH*DI];
__device__ float g_P    [4*NCHUNK*NS*DI];
__device__ float g_q    [4*NCHUNK*NS*DI];
__device__ float g_hs   [4*NCHUNK*NS*DI];
__device__ float g_stats[4];
// converted weights
__device__ bf16  g_cw_h [COUT*KIM];
__device__ bf16  g_cw_l [COUT*KIM];
__device__ bf16  g_wi_h [4*512*COUT];
__device__ bf16  g_wi_l [4*512*COUT];
__device__ bf16  g_wo_h [4*COUT*DI];
__device__ bf16  g_wo_l [4*COUT*DI];
__device__ bf16  g_wx_h [4*64*DI];   // xproj padded 40->64 rows
__device__ bf16  g_wx_l [4*64*DI];

// ---------------- helpers ----------------
__device__ __forceinline__ uint32_t smem_u32(const void* p) {
    uint32_t a;
    asm("{ .reg .u64 t; cvta.to.shared.u64 t, %1; cvt.u32.u64 %0, t; }" : "=r"(a) : "l"(p));
    return a;
}
__device__ __forceinline__ void ldm4(uint32_t* r, uint32_t a) {
    asm volatile("ldmatrix.sync.aligned.m8n8.x4.shared.b16 {%0,%1,%2,%3}, [%4];"
        : "=r"(r[0]), "=r"(r[1]), "=r"(r[2]), "=r"(r[3]) : "r"(a));
}
__device__ __forceinline__ void mma16816(float* c, const uint32_t* a, uint32_t b0, uint32_t b1) {
    asm volatile("mma.sync.aligned.m16n8k16.row.col.f32.bf16.bf16.f32 "
        "{%0,%1,%2,%3}, {%4,%5,%6,%7}, {%8,%9}, {%0,%1,%2,%3};"
        : "+f"(c[0]), "+f"(c[1]), "+f"(c[2]), "+f"(c[3])
        : "r"(a[0]), "r"(a[1]), "r"(a[2]), "r"(a[3]), "r"(b0), "r"(b1));
}
__device__ __forceinline__ void split_bf16(float x, bf16& hi, bf16& lo) {
    hi = __float2bfloat16(x);
    lo = __float2bfloat16(x - __bfloat162float(hi));
}

// =====================================================================
// HMMA NT GEMM: C[i,j] (+)= sum_k A[i,k]*B[j,k]
// A,B given as bf16 hi/lo pairs (K-major). 3-term split for ~fp32 accuracy.
// 256 threads / 8 warps. BK = 64. EPI: 0 plain(+bias), 1 bias+GN stats, 2 accum.
// =====================================================================
template<int BM, int BN, int EPI>
__global__ __launch_bounds__(256) void gemm_mma(
    const bf16* __restrict__ Ah, const bf16* __restrict__ Al, int ldk, long long aB,
    const bf16* __restrict__ Bh, const bf16* __restrict__ Bl, long long bB,
    float* __restrict__ C, int ldc, long long cB,
    int Nvalid, int K, const float* __restrict__ bias)
{
    extern __shared__ char smem[];
    constexpr int TA = BM * 64 * 2;       // bytes per A tile
    constexpr int TB = BN * 64 * 2;
    char* pAh = smem;
    char* pAl = smem + TA;
    char* pBh = smem + 2 * TA;
    char* pBl = smem + 2 * TA + TB;

    constexpr int WN = BN / 64;           // warps along N (1 or 2)
    constexpr int WM = 8 / WN;            // warps along M
    constexpr int MT = BM / (WM * 16);    // m16 tiles per warp

    const int tid = threadIdx.x, wid = tid >> 5, lane = tid & 31;
    const int wm = wid % WM, wn = wid / WM;
    const int brow = blockIdx.x * BM;
    const int bcol = blockIdx.y * BN;

    Ah += (long long)blockIdx.z * aB + (long long)brow * ldk;
    Al += (long long)blockIdx.z * aB + (long long)brow * ldk;
    Bh += (long long)blockIdx.z * bB + (long long)bcol * ldk;
    Bl += (long long)blockIdx.z * bB + (long long)bcol * ldk;
    C  += (long long)blockIdx.z * cB;

    const uint32_t sAh = smem_u32(pAh), sAl = smem_u32(pAl);
    const uint32_t sBh = smem_u32(pBh), sBl = smem_u32(pBl);

    // per-lane ldmatrix sub-offsets
    const int sub = lane >> 3, r8 = lane & 7;
    const int a_roff = (sub & 1) * 8 + r8;
    const int a_cbo  = (sub >> 1) * 16;
    const int b_noff = (sub >> 1) * 8 + r8;
    const int b_cbo  = (sub & 1) * 16;

    float c[MT][8][4];
#pragma unroll
    for (int mt = 0; mt < MT; mt++)
#pragma unroll
        for (int nt = 0; nt < 8; nt++)
#pragma unroll
            for (int j = 0; j < 4; j++) c[mt][nt][j] = 0.f;

    const int nch = K / 64;
    for (int kc = 0; kc < nch; kc++) {
        __syncthreads();
        // ---- global -> swizzled smem (all four tiles) ----
        {
            const long long koff = (long long)kc * 64;
#pragma unroll 2
            for (int v = tid; v < BM * 8; v += 256) {
                int r = v >> 3, c8 = v & 7;
                uint32_t byte = (uint32_t)(r * 128 + c8 * 16);
                byte ^= (byte >> 3) & 0x70;
                *(uint4*)(pAh + byte) = *(const uint4*)(Ah + (long long)r * ldk + koff + c8 * 8);
                *(uint4*)(pAl + byte) = *(const uint4*)(Al + (long long)r * ldk + koff + c8 * 8);
            }
#pragma unroll 2
            for (int v = tid; v < BN * 8; v += 256) {
                int r = v >> 3, c8 = v & 7;
                uint32_t byte = (uint32_t)(r * 128 + c8 * 16);
                byte ^= (byte >> 3) & 0x70;
                *(uint4*)(pBh + byte) = *(const uint4*)(Bh + (long long)r * ldk + koff + c8 * 8);
                *(uint4*)(pBl + byte) = *(const uint4*)(Bl + (long long)r * ldk + koff + c8 * 8);
            }
        }
        __syncthreads();

        // ---- 4 k-steps of 16 ----
#pragma unroll
        for (int ks = 0; ks < 4; ks++) {
            uint32_t ah[MT][4], al[MT][4];
#pragma unroll
            for (int mt = 0; mt < MT; mt++) {
                uint32_t byte = (uint32_t)((wm * MT * 16 + mt * 16 + a_roff) * 128 + ks * 32 + a_cbo);
                byte ^= (byte >> 3) & 0x70;
                ldm4(ah[mt], sAh + byte);
                ldm4(al[mt], sAl + byte);
            }
            uint32_t bhf[4][4], blf[4][4];
#pragma unroll
            for (int p = 0; p < 4; p++) {
                uint32_t byte = (uint32_t)((wn * 64 + p * 16 + b_noff) * 128 + ks * 32 + b_cbo);
                byte ^= (byte >> 3) & 0x70;
                ldm4(bhf[p], sBh + byte);
                ldm4(blf[p], sBl + byte);
            }
#pragma unroll
            for (int mt = 0; mt < MT; mt++)
#pragma unroll
                for (int nt = 0; nt < 8; nt++) {
                    uint32_t b0h = bhf[nt >> 1][(nt & 1) * 2], b1h = bhf[nt >> 1][(nt & 1) * 2 + 1];
                    uint32_t b0l = blf[nt >> 1][(nt & 1) * 2], b1l = blf[nt >> 1][(nt & 1) * 2 + 1];
                    mma16816(c[mt][nt], ah[mt], b0h, b1h);
                    mma16816(c[mt][nt], ah[mt], b0l, b1l);
                    mma16816(c[mt][nt], al[mt], b0h, b1h);
                }
        }
    }

    // ---- epilogue ----
    float sacc = 0.f, qacc = 0.f;
    const bool full = (bcol + BN <= Nvalid);
#pragma unroll
    for (int mt = 0; mt < MT; mt++) {
        int row0 = brow + wm * MT * 16 + mt * 16 + (lane >> 2);
#pragma unroll
        for (int nt = 0; nt < 8; nt++) {
            int col = bcol + wn * 64 + nt * 8 + (lane & 3) * 2;
#pragma unroll
            for (int hf = 0; hf < 2; hf++) {
                long long row = row0 + hf * 8;
                float v0 = c[mt][nt][hf * 2 + 0], v1 = c[mt][nt][hf * 2 + 1];
                if (full) {
                    if (bias) { v0 += bias[col]; v1 += bias[col + 1]; }
                    if (EPI == 2) {
                        float2 o = *(const float2*)(C + row * ldc + col);
                        v0 += o.x; v1 += o.y;
                    }
                    if (EPI == 1) { sacc += v0 + v1; qacc += v0 * v0 + v1 * v1; }
                    *(float2*)(C + row * ldc + col) = make_float2(v0, v1);
                } else {
                    if (col < Nvalid)     C[row * ldc + col]     = v0;
                    if (col + 1 < Nvalid) C[row * ldc + col + 1] = v1;
                }
            }
        }
    }

    if (EPI == 1) {
        __syncthreads();
        float* red = (float*)smem;
        red[tid] = sacc; red[256 + tid] = qacc;
        __syncthreads();
        for (int st = 128; st > 0; st >>= 1) {
            if (tid < st) { red[tid] += red[tid + st]; red[256 + tid] += red[256 + tid + st]; }
            __syncthreads();
        }
        if (tid == 0) {
            int batch = brow >> 12;
            atomicAdd(&g_stats[batch * 2 + 0], red[0]);
            atomicAdd(&g_stats[batch * 2 + 1], red[256]);
        }
    }
}

// ---------------- weight conversion ----------------
__global__ void k_cvt(const float* __restrict__ src, bf16* __restrict__ hi,
                      bf16* __restrict__ lo, int n)
{
    int i = blockIdx.x * 256 + threadIdx.x;
    if (i >= n) return;
    bf16 h, l;
    split_bf16(src[i], h, l);
    hi[i] = h; lo[i] = l;
}

__global__ void k_cvt_xproj(const float* __restrict__ src)   // [4][40][256] -> [4][64][256] padded
{
    int i = blockIdx.x * 256 + threadIdx.x;
    if (i >= 4 * 64 * DI) return;
    int m = i / (64 * DI), r = (i / DI) % 64, k = i % DI;
    float v = (r < 40) ? src[((size_t)m * 40 + r) * DI + k] : 0.f;
    bf16 h, l;
    split_bf16(v, h, l);
    g_wx_h[i] = h; g_wx_l[i] = l;
}

// ---------------- front end ----------------
__global__ void k_zero_stats() { if (threadIdx.x < 4) g_stats[threadIdx.x] = 0.f; }

__global__ void k_im2col(const float* __restrict__ x)
{
    int idx = blockIdx.x * 256 + threadIdx.x;
    if (idx >= B2 * LH * KIM) return;
    int col = idx % KIM;
    int l   = (idx / KIM) % LH;
    int b   = idx / (KIM * LH);
    int cin = col / 5, k = col % 5;
    int t = 2 * l + k - 2;
    float v = 0.f;
    if (t >= 0 && t < TFULL) v = x[((size_t)b * CIN + cin) * TFULL + t];
    bf16 h, lo;
    split_bf16(v, h, lo);
    g_im_h[idx] = h; g_im_l[idx] = lo;
}

__global__ void k_gn_apply(const float* __restrict__ gn_g, const float* __restrict__ gn_b,
                           const float* __restrict__ prelu_a)
{
    int idx = blockIdx.x * 256 + threadIdx.x;
    if (idx >= B2 * LH * COUT) return;
    int b = idx / (LH * COUT);
    int c = idx % COUT;
    const float inv = 1.f / (float)(LH * COUT);
    float mu  = g_stats[b * 2 + 0] * inv;
    float var = g_stats[b * 2 + 1] * inv - mu * mu;
    float rs  = rsqrtf(var + 1e-5f);
    float v = (g_h[idx] - mu) * rs * gn_g[c] + gn_b[c];
    float al = prelu_a[0];
    g_h[idx] = v >= 0.f ? v : al * v;
}

// ---------------- per-token LayerNorm -> bf16 hi/lo ----------------
__global__ void k_ln(const float* __restrict__ lg, const float* __restrict__ lb, int it)
{
    int gw = (blockIdx.x * blockDim.x + threadIdx.x) >> 5;
    int lane = threadIdx.x & 31;
    if (gw >= B2 * LH) return;
    const float4 v = *(const float4*)(g_h + (size_t)gw * COUT + lane * 4);
    float s = v.x + v.y + v.z + v.w;
    float q = v.x * v.x + v.y * v.y + v.z * v.z + v.w * v.w;
#pragma unroll
    for (int o = 16; o; o >>= 1) {
        s += __shfl_xor_sync(0xffffffffu, s, o);
        q += __shfl_xor_sync(0xffffffffu, q, o);
    }
    float mu  = s * (1.f / COUT);
    float var = q * (1.f / COUT) - mu * mu;
    float rs  = rsqrtf(var + 1e-5f);
    int c = lane * 4;
    const float* gg = lg + it * COUT;
    const float* gb = lb + it * COUT;
    float ov[4] = {
        (v.x - mu) * rs * gg[c+0] + gb[c+0],
        (v.y - mu) * rs * gg[c+1] + gb[c+1],
        (v.z - mu) * rs * gg[c+2] + gb[c+2],
        (v.w - mu) * rs * gg[c+3] + gb[c+3]
    };
#pragma unroll
    for (int j = 0; j < 4; j++) {
        bf16 h, lo;
        split_bf16(ov[j], h, lo);
        g_hn_h[(size_t)gw * COUT + c + j] = h;
        g_hn_l[(size_t)gw * COUT + c + j] = lo;
    }
}

// ---------------- depthwise causal conv1d + silu ----------------
__global__ void k_conv1d(const float* __restrict__ cw, const float* __restrict__ cb, int it)
{
    int idx = blockIdx.x * 256 + threadIdx.x;
    int d   = idx & 255;
    int tau = (idx >> 8) & (LH - 1);
    int b   = (idx >> 20) & 1;
    int mp  = (idx >> 21) & 1;
    int m   = 2 * it + mp;
    float acc = cb[m * DI + d];
    const float* w = cw + (size_t)(m * DI + d) * 4;
#pragma unroll
    for (int k = 0; k < 4; k++) {
        int tt = tau - 3 + k;
        if (tt >= 0) {
            int tok = mp ? (LH - 1 - tt) : tt;
            acc += w[k] * g_xz[(((size_t)b * LH + tok) * 2 + mp) * 512 + d];
        }
    }
    float u = acc / (1.f + __expf(-acc));
    g_u[idx] = u;
    bf16 h, lo;
    split_bf16(u, h, lo);
    g_u_h[idx] = h; g_u_l[idx] = lo;
}

// ---------------- delta = softplus(dt @ W_dt^T + b_dt) ----------------
__global__ __launch_bounds__(256) void k_delta(const float* __restrict__ Wd,
                                               const float* __restrict__ bd, int it)
{
    __shared__ float dts[16][8];
    int tau0 = blockIdx.x * 16;
    int b  = blockIdx.y;
    int mp = blockIdx.z;
    int m  = 2 * it + mp;
    int d  = threadIdx.x;
    if (threadIdx.x < 128) {
        int t = threadIdx.x >> 3, r = threadIdx.x & 7;
        dts[t][r] = g_xdbl[((size_t)mp * (B2 * LH) + b * LH + tau0 + t) * 40 + r];
    }
    __syncthreads();
    float w[8];
#pragma unroll
    for (int r = 0; r < 8; r++) w[r] = Wd[(size_t)(m * DI + d) * 8 + r];
    float bias = bd[m * DI + d];
    int mb = mp * 2 + b;
#pragma unroll
    for (int t = 0; t < 16; t++) {
        float p = bias;
#pragma unroll
        for (int r = 0; r < 8; r++) p += dts[t][r] * w[r];
        float dl = (p > 20.f) ? p : log1pf(__expf(p));
        g_delta[((size_t)mb * LH + tau0 + t) * DI + d] = dl;
    }
}

// ---------------- scan pass 1 ----------------
__global__ __launch_bounds__(256) void scan_pass1(const float* __restrict__ A_log, int it)
{
    int chunk = blockIdx.x, b = blockIdx.y, mp = blockIdx.z;
    int m = 2 * it + mp;
    int d = threadIdx.x;
    int mb = mp * 2 + b;
    float a[16], h[16], P[16];
#pragma unroll
    for (int n = 0; n < NS; n++) {
        a[n] = -__expf(A_log[((size_t)m * DI + d) * NS + n]);
        h[n] = 0.f; P[n] = 1.f;
    }
    __shared__ float Bsm[16][16];
    int tau0 = chunk * CHUNK;
    const float* dl = g_delta + ((size_t)mb * LH + tau0) * DI + d;
    const float* ul = g_u     + ((size_t)mb * LH + tau0) * DI + d;
    const float* xb = g_xdbl  + ((size_t)mp * (B2 * LH) + b * LH + tau0) * 40;
    for (int tt = 0; tt < CHUNK; tt += 16) {
        {
            int t = threadIdx.x >> 4, n = threadIdx.x & 15;
            Bsm[t][n] = xb[(size_t)(tt + t) * 40 + 8 + n];
        }
        __syncthreads();
#pragma unroll 4
        for (int t = 0; t < 16; t++) {
            float delta = dl[(size_t)(tt + t) * DI];
            float du = delta * ul[(size_t)(tt + t) * DI];
#pragma unroll
            for (int n = 0; n < NS; n++) {
                float dA = __expf(delta * a[n]);
                P[n] *= dA;
                h[n] = dA * h[n] + du * Bsm[t][n];
            }
        }
        __syncthreads();
    }
    size_t base = ((size_t)(mb * NCHUNK + chunk) * NS) * DI + d;
#pragma unroll
    for (int n = 0; n < NS; n++) {
        g_q[base + (size_t)n * DI] = h[n];
        g_P[base + (size_t)n * DI] = P[n];
    }
}

// ---------------- scan pass 2 ----------------
__global__ void scan_pass2()
{
    int id = blockIdx.x * 256 + threadIdx.x;
    int d  = id & 255;
    int n  = (id >> 8) & 15;
    int mb = id >> 12;
    float h = 0.f;
    for (int c = 0; c < NCHUNK; c++) {
        size_t ix = ((size_t)(mb * NCHUNK + c) * NS + n) * DI + d;
        g_hs[ix] = h;
        h = g_P[ix] * h + g_q[ix];
    }
}

// ---------------- scan pass 3 -> s (bf16 hi/lo, token order) ----------------
__global__ __launch_bounds__(256) void scan_pass3(const float* __restrict__ A_log,
                                                  const float* __restrict__ Dp, int it)
{
    int chunk = blockIdx.x, b = blockIdx.y, mp = blockIdx.z;
    int m = 2 * it + mp;
    int d = threadIdx.x;
    int mb = mp * 2 + b;
    float a[16], h[16];
#pragma unroll
    for (int n = 0; n < NS; n++) {
        a[n] = -__expf(A_log[((size_t)m * DI + d) * NS + n]);
        h[n] = g_hs[((size_t)(mb * NCHUNK + chunk) * NS + n) * DI + d];
    }
    float Dv = Dp[m * DI + d];
    __shared__ float Bsm[16][16], Csm[16][16];
    int tau0 = chunk * CHUNK;
    const float* dl = g_delta + ((size_t)mb * LH + tau0) * DI + d;
    const float* ul = g_u     + ((size_t)mb * LH + tau0) * DI + d;
    const float* xb = g_xdbl  + ((size_t)mp * (B2 * LH) + b * LH + tau0) * 40;
    for (int tt = 0; tt < CHUNK; tt += 16) {
        {
            int t = threadIdx.x >> 4, n = threadIdx.x & 15;
            Bsm[t][n] = xb[(size_t)(tt + t) * 40 + 8  + n];
            Csm[t][n] = xb[(size_t)(tt + t) * 40 + 24 + n];
        }
        __syncthreads();
#pragma unroll 4
        for (int t = 0; t < 16; t++) {
            int tau = tau0 + tt + t;
            float delta = dl[(size_t)(tt + t) * DI];
            float u = ul[(size_t)(tt + t) * DI];
            float du = delta * u;
            float y = 0.f;
#pragma unroll
            for (int n = 0; n < NS; n++) {
                float dA = __expf(delta * a[n]);
                h[n] = dA * h[n] + du * Bsm[t][n];
                y += h[n] * Csm[t][n];
            }
            int tok = mp ? (LH - 1 - tau) : tau;
            float z = g_xz[(((size_t)b * LH + tok) * 2 + mp) * 512 + 256 + d];
            float sil = z / (1.f + __expf(-z));
            float v = (y + u * Dv) * sil;
            size_t ix = ((size_t)mb * LH + tok) * DI + d;
            bf16 hh, ll;
            split_bf16(v, hh, ll);
            g_s_h[ix] = hh; g_s_l[ix] = ll;
        }
        __syncthreads();
    }
}

// ---------------- final transpose ----------------
__global__ void k_transpose(float* __restrict__ out)
{
    __shared__ float tile[32][33];
    int b = blockIdx.z;
    int l0 = blockIdx.x * 32, c0 = blockIdx.y * 32;
    int tx = threadIdx.x, ty = threadIdx.y;
#pragma unroll
    for (int j = 0; j < 32; j += 8)
        tile[ty + j][tx] = g_h[((size_t)b * LH + l0 + ty + j) * COUT + c0 + tx];
    __syncthreads();
#pragma unroll
    for (int j = 0; j < 32; j += 8)
        out[((size_t)b * COUT + c0 + ty + j) * LH + l0 + tx] = tile[tx][ty + j];
}

// ---------------- host ----------------
template<typename T>
static T* symaddr(const void* sym)
{
    void* p = nullptr;
    cudaGetSymbolAddress(&p, sym);
    return (T*)p;
}

extern "C" void kernel_launch(void* const* d_in, const int* in_sizes, int n_in,
                              void* d_out, int out_size)
{
    const float* x        = (const float*)d_in[0];
    const float* conv_w   = (const float*)d_in[1];
    const float* conv_b   = (const float*)d_in[2];
    const float* gn_g     = (const float*)d_in[3];
    const float* gn_b     = (const float*)d_in[4];
    const float* prelu_a  = (const float*)d_in[5];
    const float* ln_g     = (const float*)d_in[6];
    const float* ln_b     = (const float*)d_in[7];
    const float* W_in     = (const float*)d_in[8];
    const float* conv1d_w = (const float*)d_in[9];
    const float* conv1d_b = (const float*)d_in[10];
    const float* W_xproj  = (const float*)d_in[11];
    const float* W_dt     = (const float*)d_in[12];
    const float* b_dt     = (const float*)d_in[13];
    const float* A_log    = (const float*)d_in[14];
    const float* D_param  = (const float*)d_in[15];
    const float* W_out    = (const float*)d_in[16];
    float* out = (float*)d_out;

    auto imh = symaddr<bf16>(g_im_h);
    auto iml = symaddr<bf16>(g_im_l);
    auto hnh = symaddr<bf16>(g_hn_h);
    auto hnl = symaddr<bf16>(g_hn_l);
    auto uh  = symaddr<bf16>(g_u_h);
    auto ul  = symaddr<bf16>(g_u_l);
    auto sh  = symaddr<bf16>(g_s_h);
    auto sl  = symaddr<bf16>(g_s_l);
    auto cwh = symaddr<bf16>(g_cw_h);
    auto cwl = symaddr<bf16>(g_cw_l);
    auto wih = symaddr<bf16>(g_wi_h);
    auto wil = symaddr<bf16>(g_wi_l);
    auto woh = symaddr<bf16>(g_wo_h);
    auto wol = symaddr<bf16>(g_wo_l);
    auto wxh = symaddr<bf16>(g_wx_h);
    auto wxl = symaddr<bf16>(g_wx_l);
    auto ph   = symaddr<float>(g_h);
    auto pxz  = symaddr<float>(g_xz);
    auto pxd  = symaddr<float>(g_xdbl);

    // smem sizes: (BM+BN)*256 bytes
    cudaFuncSetAttribute(gemm_mma<64,128,1>,  cudaFuncAttributeMaxDynamicSharedMemorySize, 49152);
    cudaFuncSetAttribute(gemm_mma<128,128,0>, cudaFuncAttributeMaxDynamicSharedMemorySize, 65536);
    cudaFuncSetAttribute(gemm_mma<128,64,0>,  cudaFuncAttributeMaxDynamicSharedMemorySize, 49152);
    cudaFuncSetAttribute(gemm_mma<64,128,2>,  cudaFuncAttributeMaxDynamicSharedMemorySize, 49152);

    const int M = B2 * LH;   // 8192

    // ---- weight conversions (tiny) ----
    k_zero_stats<<<1, 32>>>();
    k_cvt<<<(COUT*KIM + 255)/256, 256>>>(conv_w, cwh, cwl, COUT*KIM);
    k_cvt<<<(4*512*COUT + 255)/256, 256>>>(W_in, wih, wil, 4*512*COUT);
    k_cvt<<<(4*COUT*DI + 255)/256, 256>>>(W_out, woh, wol, 4*COUT*DI);
    k_cvt_xproj<<<(4*64*DI + 255)/256, 256>>>(W_xproj);

    // ---- front end: conv GEMM (M=8192,N=128,K=320) + fused GN stats ----
    k_im2col<<<(B2 * LH * KIM + 255) / 256, 256>>>(x);
    gemm_mma<64,128,1><<<dim3(M/64, 1, 1), 256, 49152>>>(
        imh, iml, KIM, 0, cwh, cwl, 0, ph, COUT, 0, COUT, KIM, conv_b);
    k_gn_apply<<<(B2 * LH * COUT + 255) / 256, 256>>>(gn_g, gn_b, prelu_a);

    // ---- bidirectional mamba blocks ----
    for (int it = 0; it < NITER; ++it) {
        k_ln<<<(M * 32 + 255) / 256, 256>>>(ln_g, ln_b, it);

        // xz = hn @ W_in^T : N=1024, K=128
        gemm_mma<128,128,0><<<dim3(M/128, 1024/128, 1), 256, 65536>>>(
            hnh, hnl, COUT, 0,
            wih + (size_t)it * 1024 * COUT, wil + (size_t)it * 1024 * COUT, 0,
            pxz, 1024, 0, 1024, COUT, nullptr);

        k_conv1d<<<(2 * B2 * LH * DI) / 256, 256>>>(conv1d_w, conv1d_b, it);

        // xdbl = u @ W_xproj^T : N=40 (padded 64), K=256, batched over direction
        gemm_mma<128,64,0><<<dim3(M/128, 1, 2), 256, 49152>>>(
            uh, ul, DI, (long long)2 * LH * DI,
            wxh + (size_t)(2*it) * 64 * DI, wxl + (size_t)(2*it) * 64 * DI, (long long)64 * DI,
            pxd, 40, (long long)B2 * LH * 40,
            40, DI, nullptr);

        k_delta<<<dim3(LH / 16, B2, 2), 256>>>(W_dt, b_dt, it);

        scan_pass1<<<dim3(NCHUNK, B2, 2), 256>>>(A_log, it);
        scan_pass2<<<64, 256>>>();
        scan_pass3<<<dim3(NCHUNK, B2, 2), 256>>>(A_log, D_param, it);

        // h += s @ W_out^T : N=128, K=256 (sequential: both accumulate into g_h)
        for (int mp = 0; mp < 2; mp++) {
            int m = 2 * it + mp;
            gemm_mma<64,128,2><<<dim3(M/64, 1, 1), 256, 49152>>>(
                sh + (size_t)mp * 2 * LH * DI, sl + (size_t)mp * 2 * LH * DI, DI, 0,
                woh + (size_t)m * COUT * DI, wol + (size_t)m * COUT * DI, 0,
                ph, COUT, 0, COUT, DI, nullptr);
        }
    }

    k_transpose<<<dim3(LH / 32, COUT / 32, B2), dim3(32, 8)>>>(out);
}